// round 1
// baseline (speedup 1.0000x reference)
#include <cuda_runtime.h>

// DigitCaps dynamic routing, fully fused.
// Shapes: u[B=256, N=1152, IC=8], W[K=10, N=1152, IC=8, OC=16]
// out: v [K, B, 1, 1, OC] = 10*256*16 = 40960 floats.
//
// One block handles (k, b0..b0+1). 512 threads = 16 warps.
// Lane layout: o = lane & 15 (output channel), sub = lane >> 4.
// Thread (w, sub, o) owns u_hat[bi][n_j][o] for n_j = (j*16 + w)*2 + sub, j=0..35.
// W is read once per block from L2 (fits entirely in L2) and reused for both batches.
// Routing logits b[n] kept in shared memory (identical across o-channels).

#define K_CAPS 10
#define BATCH  256
#define NN     1152
#define IC     8
#define OC     16
#define NWARP  16
#define THREADS (NWARP * 32)
#define J      36      // n-steps per (warp, sub):  NN / (NWARP*2)
#define BPB    2       // batches per block

__global__ __launch_bounds__(THREADS, 1)
void digitcaps_kernel(const float* __restrict__ u,
                      const float* __restrict__ W,
                      float* __restrict__ out) {
    const int k    = blockIdx.y;
    const int b0   = blockIdx.x * BPB;
    const int tid  = threadIdx.x;
    const int w    = tid >> 5;
    const int lane = tid & 31;
    const int o    = lane & 15;
    const int sub  = lane >> 4;

    __shared__ float bb_s[BPB][NN];      // routing logits per (batch, n)
    __shared__ float red[NWARP];         // block-reduce scratch
    __shared__ float sP[NWARP][OC];      // per-warp partial s vectors

    // init routing logits to zero
    for (int i = tid; i < BPB * NN; i += THREADS)
        (&bb_s[0][0])[i] = 0.0f;

    // ---- compute u_hat into registers ----
    float uh[BPB][J];
    const float* Wk = W + (size_t)k * NN * IC * OC;

    #pragma unroll
    for (int j = 0; j < J; ++j) {
        const int n = ((j * NWARP + w) << 1) + sub;
        const float* Wrow = Wk + n * (IC * OC) + o;      // stride OC per i
        const float4* u0p = (const float4*)(u + ((size_t)(b0 + 0) * NN + n) * IC);
        const float4* u1p = (const float4*)(u + ((size_t)(b0 + 1) * NN + n) * IC);
        float4 a0 = u0p[0], a1 = u0p[1];                 // broadcast loads (same addr across o-lanes)
        float4 c0 = u1p[0], c1 = u1p[1];
        float acc0 = 0.0f, acc1 = 0.0f;
        float wv;
        wv = Wrow[0 * OC]; acc0 += a0.x * wv; acc1 += c0.x * wv;
        wv = Wrow[1 * OC]; acc0 += a0.y * wv; acc1 += c0.y * wv;
        wv = Wrow[2 * OC]; acc0 += a0.z * wv; acc1 += c0.z * wv;
        wv = Wrow[3 * OC]; acc0 += a0.w * wv; acc1 += c0.w * wv;
        wv = Wrow[4 * OC]; acc0 += a1.x * wv; acc1 += c1.x * wv;
        wv = Wrow[5 * OC]; acc0 += a1.y * wv; acc1 += c1.y * wv;
        wv = Wrow[6 * OC]; acc0 += a1.z * wv; acc1 += c1.z * wv;
        wv = Wrow[7 * OC]; acc0 += a1.w * wv; acc1 += c1.w * wv;
        uh[0][j] = acc0;
        uh[1][j] = acc1;
    }
    __syncthreads();

    // ---- 3 routing iterations ----
    for (int it = 0; it < 3; ++it) {
        #pragma unroll
        for (int bi = 0; bi < BPB; ++bi) {
            // phase 1: max over N of logits (for softmax stability)
            float m = -1e30f;
            #pragma unroll
            for (int j = 0; j < J; ++j) {
                const int n = ((j * NWARP + w) << 1) + sub;
                m = fmaxf(m, bb_s[bi][n]);
            }
            #pragma unroll
            for (int d = 16; d >= 1; d >>= 1)
                m = fmaxf(m, __shfl_xor_sync(0xffffffffu, m, d));
            if (lane == 0) red[w] = m;
            __syncthreads();
            float M = red[0];
            #pragma unroll
            for (int i = 1; i < NWARP; ++i) M = fmaxf(M, red[i]);
            __syncthreads();

            // phase 2: e = exp(b - M), sum of e, unnormalized s accumulation
            float esum = 0.0f, sU = 0.0f;
            #pragma unroll
            for (int j = 0; j < J; ++j) {
                const int n = ((j * NWARP + w) << 1) + sub;
                float e = __expf(bb_s[bi][n] - M);
                esum += e;
                sU += e * uh[bi][j];
            }
            // block-sum esum over all lanes: each n counted 16x (o-duplication) -> S16 = 16*S
            #pragma unroll
            for (int d = 16; d >= 1; d >>= 1)
                esum += __shfl_xor_sync(0xffffffffu, esum, d);
            if (lane == 0) red[w] = esum;
            __syncthreads();
            float S16 = 0.0f;
            #pragma unroll
            for (int i = 0; i < NWARP; ++i) S16 += red[i];
            __syncthreads();

            // reduce sU across threads sharing the same o
            sU += __shfl_xor_sync(0xffffffffu, sU, 16);   // across sub
            if (sub == 0) sP[w][o] = sU;
            __syncthreads();
            float s = 0.0f;
            #pragma unroll
            for (int ww = 0; ww < NWARP; ++ww) s += sP[ww][o];
            s *= 16.0f / S16;                              // s_o = (sum_n e_n uh_n)/S
            __syncthreads();

            // squash: sq = sum_o s_o^2 (reduce over o bits 0..3)
            float sq = s * s;
            sq += __shfl_xor_sync(0xffffffffu, sq, 1);
            sq += __shfl_xor_sync(0xffffffffu, sq, 2);
            sq += __shfl_xor_sync(0xffffffffu, sq, 4);
            sq += __shfl_xor_sync(0xffffffffu, sq, 8);
            float scale = sq / ((1.0f + sq) * sqrtf(sq));
            float v = s * scale;

            if (it < 2) {
                // a_j = <uh_j, v> (reduce over o), update logits
                #pragma unroll
                for (int j = 0; j < J; ++j) {
                    float p = uh[bi][j] * v;
                    p += __shfl_xor_sync(0xffffffffu, p, 1);
                    p += __shfl_xor_sync(0xffffffffu, p, 2);
                    p += __shfl_xor_sync(0xffffffffu, p, 4);
                    p += __shfl_xor_sync(0xffffffffu, p, 8);
                    if (o == 0) {
                        const int n = ((j * NWARP + w) << 1) + sub;
                        bb_s[bi][n] += p;
                    }
                }
                __syncthreads();
            } else {
                // final: write v for this (k, b0+bi)
                if (w == 0 && sub == 0) {
                    out[((size_t)k * BATCH + (b0 + bi)) * OC + o] = v;
                }
            }
        }
    }
}

extern "C" void kernel_launch(void* const* d_in, const int* in_sizes, int n_in,
                              void* d_out, int out_size) {
    const float* u = (const float*)d_in[0];
    const float* W = (const float*)d_in[1];
    // defensive: identify by element count (u: 2359296, W: 1474560)
    if (n_in >= 2 && in_sizes[0] == K_CAPS * NN * IC * OC) {
        const float* t = u; u = W; W = t;
    }
    float* out = (float*)d_out;

    dim3 grid(BATCH / BPB, K_CAPS);
    digitcaps_kernel<<<grid, THREADS>>>(u, W, out);
}

// round 2
// speedup vs baseline: 1.0188x; 1.0188x over previous
#include <cuda_runtime.h>

// DigitCaps dynamic routing, fully fused, BPB=4.
// u[B=256, N=1152, IC=8], W[K=10, N=1152, IC=8, OC=16] -> v [K, B, 1, 1, OC]
//
// Grid: (B/4, K). Block: 512 threads = 16 warps.
// Lane layout: o = lane & 15 (output channel), sub = lane >> 4.
// Thread (w, sub, o) owns n_j = (j*16 + w)*2 + sub, j = 0..35.
// u_hat for batches 0,1 in registers; batches 2,3 in smem (conflict-free [n][o]).
// W read once per block (L2-resident), amortized over 4 batches.
// Iteration 0 uses uniform softmax shortcut; softmax max tracked during the
// logit update (no separate max pass). Block reductions via red[o] + shfl trees.

#define K_CAPS 10
#define BATCH  256
#define NN     1152
#define IC     8
#define OC     16
#define NWARP  16
#define THREADS 512
#define J      36
#define BPB    4
#define RB     2   // register-resident batches

#define NJ(j) ((((j) * NWARP + w) << 1) + sub)

__global__ __launch_bounds__(THREADS, 1)
void digitcaps_kernel(const float* __restrict__ u,
                      const float* __restrict__ W,
                      float* __restrict__ out)
{
    extern __shared__ float smem[];
    float* bb   = smem;                         // [BPB][NN] routing logits
    float* uh_s = bb + BPB * NN;                // [BPB-RB][NN][OC]
    float* red  = uh_s + (BPB - RB) * NN * OC;  // [NWARP]
    float* sPm  = red + NWARP;                  // [NWARP][OC]
    float* redM = sPm + NWARP * OC;             // [NWARP][BPB]

    const int k    = blockIdx.y;
    const int b0   = blockIdx.x * BPB;
    const int tid  = threadIdx.x;
    const int w    = tid >> 5;
    const int lane = tid & 31;
    const int o    = lane & 15;
    const int sub  = lane >> 4;
    const unsigned FULL = 0xffffffffu;

    // ---- u_hat: 2 batches -> registers, 2 batches -> smem ----
    float uh_r[RB][J];
    const float* Wk = W + (size_t)k * (NN * IC * OC);

    #pragma unroll
    for (int j = 0; j < J; ++j) {
        const int n = NJ(j);
        const float* Wrow = Wk + n * (IC * OC) + o;
        float w0 = Wrow[0*OC], w1 = Wrow[1*OC], w2 = Wrow[2*OC], w3 = Wrow[3*OC];
        float w4 = Wrow[4*OC], w5 = Wrow[5*OC], w6 = Wrow[6*OC], w7 = Wrow[7*OC];
        #pragma unroll
        for (int bi = 0; bi < BPB; ++bi) {
            const float4* up = (const float4*)(u + ((size_t)(b0 + bi) * NN + n) * IC);
            float4 x0 = up[0], x1 = up[1];
            float acc = x0.x*w0 + x0.y*w1 + x0.z*w2 + x0.w*w3
                      + x1.x*w4 + x1.y*w5 + x1.z*w6 + x1.w*w7;
            if (bi < RB) uh_r[bi][j] = acc;
            else uh_s[(((bi - RB) * NN) + n) * OC + o] = acc;
        }
    }
    __syncthreads();

    // ---- 3 routing iterations ----
    #pragma unroll 1
    for (int it = 0; it < 3; ++it) {
        #pragma unroll
        for (int bi = 0; bi < BPB; ++bi) {
            float esum = 0.0f, sU = 0.0f;
            if (it == 0) {
                // b == 0 -> uniform c: s = mean(uh)
                #pragma unroll
                for (int j = 0; j < J; ++j) {
                    float uh = (bi < RB) ? uh_r[bi][j]
                             : uh_s[(((bi - RB) * NN) + NJ(j)) * OC + o];
                    sU += uh;
                }
            } else {
                // block max of b (tracked during previous update)
                float M = redM[o * BPB + bi];
                M = fmaxf(M, __shfl_xor_sync(FULL, M, 1));
                M = fmaxf(M, __shfl_xor_sync(FULL, M, 2));
                M = fmaxf(M, __shfl_xor_sync(FULL, M, 4));
                M = fmaxf(M, __shfl_xor_sync(FULL, M, 8));
                #pragma unroll
                for (int j = 0; j < J; ++j) {
                    const int n = NJ(j);
                    float e = __expf(bb[bi * NN + n] - M);
                    float uh = (bi < RB) ? uh_r[bi][j]
                             : uh_s[(((bi - RB) * NN) + n) * OC + o];
                    esum += e;
                    sU = fmaf(e, uh, sU);
                }
                #pragma unroll
                for (int d = 16; d >= 1; d >>= 1)
                    esum += __shfl_xor_sync(FULL, esum, d);
                if (lane == 0) red[w] = esum;   // = 16 * (warp's true esum)
            }
            sU += __shfl_xor_sync(FULL, sU, 16);
            if (sub == 0) sPm[w * OC + o] = sU;
            __syncthreads();

            float S;
            if (it == 0) {
                S = (float)NN;
            } else {
                float t = red[o];                // o spans the 16 warps
                t += __shfl_xor_sync(FULL, t, 1);
                t += __shfl_xor_sync(FULL, t, 2);
                t += __shfl_xor_sync(FULL, t, 4);
                t += __shfl_xor_sync(FULL, t, 8);
                S = t * (1.0f / 16.0f);
            }
            float s = 0.0f;
            #pragma unroll
            for (int r = 0; r < 8; ++r)
                s += sPm[(sub * 8 + r) * OC + o];
            s += __shfl_xor_sync(FULL, s, 16);
            s /= S;

            // squash
            float sq = s * s;
            sq += __shfl_xor_sync(FULL, sq, 1);
            sq += __shfl_xor_sync(FULL, sq, 2);
            sq += __shfl_xor_sync(FULL, sq, 4);
            sq += __shfl_xor_sync(FULL, sq, 8);
            float v = s * (sq / ((1.0f + sq) * sqrtf(sq)));

            if (it < 2) {
                // b += <uh, v>, track running max for next iteration's softmax
                float m = -1e30f;
                #pragma unroll
                for (int j = 0; j < J; ++j) {
                    const int n = NJ(j);
                    float uh = (bi < RB) ? uh_r[bi][j]
                             : uh_s[(((bi - RB) * NN) + n) * OC + o];
                    float p = uh * v;
                    p += __shfl_xor_sync(FULL, p, 1);
                    p += __shfl_xor_sync(FULL, p, 2);
                    p += __shfl_xor_sync(FULL, p, 4);
                    p += __shfl_xor_sync(FULL, p, 8);
                    float bn = (it == 0) ? p : (bb[bi * NN + n] + p);
                    m = fmaxf(m, bn);
                    if (o == 0) bb[bi * NN + n] = bn;
                }
                m = fmaxf(m, __shfl_xor_sync(FULL, m, 16));
                if (lane == 0) redM[w * BPB + bi] = m;
                __syncthreads();
            } else {
                if (w == 0 && sub == 0)
                    out[((size_t)k * BATCH + (b0 + bi)) * OC + o] = v;
                __syncthreads();
            }
        }
    }
}

extern "C" void kernel_launch(void* const* d_in, const int* in_sizes, int n_in,
                              void* d_out, int out_size) {
    const float* u = (const float*)d_in[0];
    const float* W = (const float*)d_in[1];
    if (n_in >= 2 && in_sizes[0] == K_CAPS * NN * IC * OC) {
        const float* t = u; u = W; W = t;
    }
    float* out = (float*)d_out;

    const int smem_bytes = (BPB * NN + (BPB - RB) * NN * OC
                            + NWARP + NWARP * OC + NWARP * BPB) * (int)sizeof(float);
    cudaFuncSetAttribute(digitcaps_kernel,
                         cudaFuncAttributeMaxDynamicSharedMemorySize, smem_bytes);

    dim3 grid(BATCH / BPB, K_CAPS);
    digitcaps_kernel<<<grid, THREADS, smem_bytes>>>(u, W, out);
}

// round 3
// speedup vs baseline: 1.1193x; 1.0986x over previous
#include <cuda_runtime.h>
#include <cuda_fp16.h>

// DigitCaps dynamic routing — row-per-thread, shfl-free routing, fp16 u_hat in smem.
// u[B=256, N=1152, IC=8], W[K=10, N=1152, IC=8, OC=16] -> v [K, B, 1, 1, 16]
//
// Grid (B/4, K); block 576 threads (18 warps), 1 block/SM (203 KB smem).
// Thread t owns rows n = 2t, 2t+1 (full 16-o rows): logits b_n in registers,
// exp once per n, a_n = <uh_n, v> as 16 register FMAs (no shuffles).
// s_o accumulation in a (seg, o-pair) layout with half2 loads; warp 0 finalizes
// (sum partials, divide by esum, squash) and broadcasts v via smem.
// Softmax max-subtraction omitted: logits bounded (|b| < ~40), exp safe in fp32.

#define K_CAPS 10
#define BATCH  256
#define NN     1152
#define IC     8
#define OC     16
#define THREADS 576
#define NWARP  18
#define BPB    4
#define RST    18          // halves per uh row (16 + 2 pad, kills bank conflicts)
#define NSEG   72          // s-phase segments (16 n each)

__global__ __launch_bounds__(THREADS, 1)
void digitcaps_kernel(const float* __restrict__ u,
                      const float* __restrict__ W,
                      float* __restrict__ out)
{
    extern __shared__ char smem_raw[];
    half*  uh   = (half*)smem_raw;                          // [BPB][NN][RST]
    float* eb   = (float*)(uh + BPB * NN * RST);            // [BPB][NN]
    float* sp   = eb + BPB * NN;                            // [BPB][NSEG][16]
    float* vs   = sp + BPB * NSEG * 16;                     // [BPB][16]
    float* redE = vs + BPB * 16;                            // [BPB][NWARP]

    const int k    = blockIdx.y;
    const int b0   = blockIdx.x * BPB;
    const int t    = threadIdx.x;
    const int lane = t & 31;
    const int w    = t >> 5;
    const int n0   = 2 * t;
    const int op   = t & 7;        // o-pair index for s-phase
    const int seg  = t >> 3;       // 0..71
    const unsigned FULL = 0xffffffffu;

    float brow[BPB][2];
    #pragma unroll
    for (int bi = 0; bi < BPB; ++bi) { brow[bi][0] = 0.0f; brow[bi][1] = 0.0f; }

    // ---------------- u_hat phase ----------------
    const float* Wk = W + (size_t)k * NN * (IC * OC);
    #pragma unroll
    for (int r = 0; r < 2; ++r) {
        const int n = n0 + r;
        const float4* Wrow = (const float4*)(Wk + (size_t)n * (IC * OC));
        float4 u4[BPB][2];
        #pragma unroll
        for (int bi = 0; bi < BPB; ++bi) {
            const float4* up = (const float4*)(u + ((size_t)(b0 + bi) * NN + n) * IC);
            u4[bi][0] = up[0];
            u4[bi][1] = up[1];
        }
        #pragma unroll
        for (int og = 0; og < 4; ++og) {
            float4 acc[BPB];
            #pragma unroll
            for (int bi = 0; bi < BPB; ++bi) acc[bi] = make_float4(0.f, 0.f, 0.f, 0.f);
            #pragma unroll
            for (int i = 0; i < 8; ++i) {
                float4 wv = Wrow[i * 4 + og];
                #pragma unroll
                for (int bi = 0; bi < BPB; ++bi) {
                    float ui = ((const float*)&u4[bi][0])[i];
                    acc[bi].x = fmaf(ui, wv.x, acc[bi].x);
                    acc[bi].y = fmaf(ui, wv.y, acc[bi].y);
                    acc[bi].z = fmaf(ui, wv.z, acc[bi].z);
                    acc[bi].w = fmaf(ui, wv.w, acc[bi].w);
                }
            }
            #pragma unroll
            for (int bi = 0; bi < BPB; ++bi) {
                half2* dst = (half2*)(uh + ((size_t)bi * NN + n) * RST + og * 4);
                dst[0] = __floats2half2_rn(acc[bi].x, acc[bi].y);
                dst[1] = __floats2half2_rn(acc[bi].z, acc[bi].w);
            }
        }
    }
    __syncthreads();

    // ---------------- routing iterations ----------------
    #pragma unroll 1
    for (int it = 0; it < 3; ++it) {
        // e-phase (it >= 1): e_n = exp(b_n), partial esum per warp
        if (it > 0) {
            #pragma unroll
            for (int bi = 0; bi < BPB; ++bi) {
                float e0 = __expf(brow[bi][0]);
                float e1 = __expf(brow[bi][1]);
                eb[bi * NN + n0]     = e0;
                eb[bi * NN + n0 + 1] = e1;
                float es = e0 + e1;
                #pragma unroll
                for (int d = 16; d >= 1; d >>= 1)
                    es += __shfl_xor_sync(FULL, es, d);
                if (lane == 0) redE[bi * NWARP + w] = es;
            }
            __syncthreads();
        }

        // s-phase: thread (seg, op) accumulates s over n = seg*16 .. +15 for o = 2op, 2op+1
        #pragma unroll
        for (int bi = 0; bi < BPB; ++bi) {
            const half*  uhb = uh + (size_t)bi * NN * RST;
            const float* ebb = eb + bi * NN;
            float s0 = 0.0f, s1 = 0.0f;
            #pragma unroll
            for (int i = 0; i < 16; ++i) {
                const int n = seg * 16 + i;
                float2 p = __half22float2(*(const half2*)(uhb + n * RST + op * 2));
                if (it == 0) {
                    s0 += p.x; s1 += p.y;
                } else {
                    float e = ebb[n];
                    s0 = fmaf(e, p.x, s0);
                    s1 = fmaf(e, p.y, s1);
                }
            }
            *(float2*)(sp + ((size_t)bi * NSEG + seg) * 16 + op * 2) = make_float2(s0, s1);
        }
        __syncthreads();

        // final phase: warp 0 (lane = o + 16h) reduces 72 partials, squash, emit v
        if (w == 0) {
            const int o = lane & 15, h = lane >> 4;
            #pragma unroll
            for (int bi = 0; bi < BPB; ++bi) {
                float a0 = 0.0f, a1 = 0.0f;
                #pragma unroll
                for (int q = 0; q < 36; q += 2) {
                    a0 += sp[((size_t)bi * NSEG + h * 36 + q) * 16 + o];
                    a1 += sp[((size_t)bi * NSEG + h * 36 + q + 1) * 16 + o];
                }
                float acc = a0 + a1;
                acc += __shfl_xor_sync(FULL, acc, 16);
                float S;
                if (it == 0) {
                    S = (float)NN;
                } else {
                    S = 0.0f;
                    #pragma unroll
                    for (int q = 0; q < NWARP; ++q) S += redE[bi * NWARP + q];
                }
                float s = acc / S;
                float sq = s * s;
                sq += __shfl_xor_sync(FULL, sq, 1);
                sq += __shfl_xor_sync(FULL, sq, 2);
                sq += __shfl_xor_sync(FULL, sq, 4);
                sq += __shfl_xor_sync(FULL, sq, 8);
                float vv = s * (sq / ((1.0f + sq) * sqrtf(sq)));
                if (h == 0) {
                    if (it == 2)
                        out[((size_t)k * BATCH + (b0 + bi)) * OC + o] = vv;
                    else
                        vs[bi * 16 + o] = vv;
                }
            }
        }
        if (it == 2) break;          // done: warp 0 wrote outputs
        __syncthreads();

        // a-phase: b_n += <uh_n, v>  (all in registers, no shuffles)
        #pragma unroll
        for (int bi = 0; bi < BPB; ++bi) {
            const float4* vp = (const float4*)(vs + bi * 16);
            float4 v0 = vp[0], v1 = vp[1], v2 = vp[2], v3 = vp[3];
            #pragma unroll
            for (int r = 0; r < 2; ++r) {
                const half2* row = (const half2*)(uh + ((size_t)bi * NN + n0 + r) * RST);
                float2 q;
                float a = 0.0f;
                q = __half22float2(row[0]); a = fmaf(q.x, v0.x, a); a = fmaf(q.y, v0.y, a);
                q = __half22float2(row[1]); a = fmaf(q.x, v0.z, a); a = fmaf(q.y, v0.w, a);
                q = __half22float2(row[2]); a = fmaf(q.x, v1.x, a); a = fmaf(q.y, v1.y, a);
                q = __half22float2(row[3]); a = fmaf(q.x, v1.z, a); a = fmaf(q.y, v1.w, a);
                q = __half22float2(row[4]); a = fmaf(q.x, v2.x, a); a = fmaf(q.y, v2.y, a);
                q = __half22float2(row[5]); a = fmaf(q.x, v2.z, a); a = fmaf(q.y, v2.w, a);
                q = __half22float2(row[6]); a = fmaf(q.x, v3.x, a); a = fmaf(q.y, v3.y, a);
                q = __half22float2(row[7]); a = fmaf(q.x, v3.z, a); a = fmaf(q.y, v3.w, a);
                brow[bi][r] += a;
            }
        }
        // no barrier: next e-phase uses this thread's own registers; eb/sp are
        // re-synchronized by the e-phase / s-phase barriers above.
    }
}

extern "C" void kernel_launch(void* const* d_in, const int* in_sizes, int n_in,
                              void* d_out, int out_size) {
    const float* u = (const float*)d_in[0];
    const float* W = (const float*)d_in[1];
    if (n_in >= 2 && in_sizes[0] == K_CAPS * NN * IC * OC) {
        const float* tp = u; u = W; W = tp;
    }
    float* out = (float*)d_out;

    const int smem_bytes =
        BPB * NN * RST * (int)sizeof(half)        // uh
        + BPB * NN * (int)sizeof(float)           // eb
        + BPB * NSEG * 16 * (int)sizeof(float)    // sp
        + BPB * 16 * (int)sizeof(float)           // vs
        + BPB * NWARP * (int)sizeof(float);       // redE

    cudaFuncSetAttribute(digitcaps_kernel,
                         cudaFuncAttributeMaxDynamicSharedMemorySize, smem_bytes);

    dim3 grid(BATCH / BPB, K_CAPS);
    digitcaps_kernel<<<grid, THREADS, smem_bytes>>>(u, W, out);
}

// round 4
// speedup vs baseline: 1.5322x; 1.3690x over previous
#include <cuda_runtime.h>
#include <cuda_fp16.h>

// DigitCaps routing, 3-kernel streaming pipeline with fp16 u_hat scratch.
// u[B=256, N=1152, IC=8], W[K=10, N=1152, IC=8, OC=16] -> v [K, B, 1, 1, 16]
//
// K1:    u_hat (fp16) -> g_uh[k][b][n][o], plus iteration-0 sums s0 (no atomics:
//        each block owns 8 full batches across all N).
// Kpass: one routing iteration per launch. Block = one (k,b): compute
//        v = squash(s_prev/esum_prev), stream uh rows, a=<uh,v>, b+=a, e=exp(b),
//        accumulate s,esum, block-reduce. Pass 2 writes final output directly.

#define KC 10
#define BB 256
#define NN 1152
#define IC 8
#define OC 16
#define BCH 8          // K1: batches per block
#define NCH 128        // K1: n per staged chunk

__device__ __align__(16) half g_uh[(size_t)KC * BB * NN * OC];  // 94.4 MB
__device__ float g_b [KC * BB * NN];                            // 11.8 MB
__device__ float g_s [KC * BB * OC];
__device__ float g_es[KC * BB];

// ---------------- K1: u_hat + s0 ----------------
__global__ __launch_bounds__(512, 2)
void k_uhat(const float* __restrict__ u, const float* __restrict__ W)
{
    __shared__ float us_raw[BCH * NCH * IC];   // 32 KB, reused for s0 reduce
    float (*us)[NCH][IC] = (float (*)[NCH][IC])us_raw;

    const int k  = blockIdx.y;
    const int b0 = blockIdx.x * BCH;
    const int t  = threadIdx.x;
    const int o  = t & 15;
    const int ns = t >> 4;        // 0..31

    float s0[BCH];
    #pragma unroll
    for (int i = 0; i < BCH; ++i) s0[i] = 0.0f;

    for (int c = 0; c < NN / NCH; ++c) {
        __syncthreads();
        // stage u[b0..b0+7][c*128..+127][0..7] (coalesced float4)
        #pragma unroll
        for (int q = 0; q < 4; ++q) {
            int idx = t + q * 512;                 // 0..2047 float4 slots
            int bb = idx >> 8, r = idx & 255, nn = r >> 1, h = r & 1;
            const float4* src =
                (const float4*)(u + ((size_t)(b0 + bb) * NN + c * NCH + nn) * IC);
            *(float4*)&us[bb][nn][h * 4] = src[h];
        }
        __syncthreads();
        #pragma unroll
        for (int j = 0; j < 4; ++j) {
            const int nn = j * 32 + ns;
            const int n  = c * NCH + nn;
            const float* Wr = W + ((size_t)(k * NN + n)) * (IC * OC) + o;
            float w0 = Wr[0],  w1 = Wr[16], w2 = Wr[32],  w3 = Wr[48];
            float w4 = Wr[64], w5 = Wr[80], w6 = Wr[96],  w7 = Wr[112];
            #pragma unroll
            for (int bb = 0; bb < BCH; ++bb) {
                float4 a0 = *(const float4*)&us[bb][nn][0];
                float4 a1 = *(const float4*)&us[bb][nn][4];
                float acc = a0.x*w0 + a0.y*w1 + a0.z*w2 + a0.w*w3
                          + a1.x*w4 + a1.y*w5 + a1.z*w6 + a1.w*w7;
                s0[bb] += acc;
                g_uh[((size_t)(k * BB + b0 + bb) * NN + n) * OC + o] =
                    __float2half_rn(acc);
            }
        }
    }

    // s0 reduce over the 32 ns-threads per (b,o); reuse staging smem
    __syncthreads();
    float (*red)[32][OC] = (float (*)[32][OC])us_raw;   // 4096 floats <= 8192
    #pragma unroll
    for (int bb = 0; bb < BCH; ++bb) red[bb][ns][o] = s0[bb];
    __syncthreads();
    if (t < BCH * OC) {
        int bb = t >> 4, oo = t & 15;
        float s = 0.0f;
        #pragma unroll
        for (int i = 0; i < 32; ++i) s += red[bb][i][oo];
        g_s[(k * BB + b0 + bb) * OC + oo] = s;   // sum over n (uniform-c iter)
    }
}

// ---------------- Kpass: one routing iteration ----------------
__global__ __launch_bounds__(512, 2)
void k_pass(float* __restrict__ out, int pass)
{
    const int kb   = blockIdx.x;          // k*256 + b
    const int t    = threadIdx.x;
    const int w    = t >> 5;
    const int lane = t & 31;
    const unsigned FULL = 0xffffffffu;

    // v = squash(s_prev / esum_prev), computed redundantly per thread
    const float S = (pass == 1) ? (float)NN : g_es[kb];
    float v[OC];
    float sq = 0.0f;
    #pragma unroll
    for (int o = 0; o < OC; ++o) {
        float x = g_s[kb * OC + o] / S;
        v[o] = x;
        sq += x * x;
    }
    const float scl = sq / ((1.0f + sq) * sqrtf(sq));
    #pragma unroll
    for (int o = 0; o < OC; ++o) v[o] *= scl;

    float sa[OC];
    #pragma unroll
    for (int o = 0; o < OC; ++o) sa[o] = 0.0f;
    float es = 0.0f;

    for (int n = t; n < NN; n += 512) {
        const uint4* rp = (const uint4*)(g_uh + ((size_t)kb * NN + n) * OC);
        uint4 r0 = rp[0], r1 = rp[1];
        float uhv[OC];
        const half2* h0 = (const half2*)&r0;
        const half2* h1 = (const half2*)&r1;
        #pragma unroll
        for (int i = 0; i < 4; ++i) {
            float2 p = __half22float2(h0[i]);
            uhv[2*i] = p.x; uhv[2*i + 1] = p.y;
        }
        #pragma unroll
        for (int i = 0; i < 4; ++i) {
            float2 p = __half22float2(h1[i]);
            uhv[8 + 2*i] = p.x; uhv[8 + 2*i + 1] = p.y;
        }
        float a = 0.0f;
        #pragma unroll
        for (int o = 0; o < OC; ++o) a = fmaf(uhv[o], v[o], a);
        float bn;
        if (pass == 1) { bn = a; g_b[kb * NN + n] = bn; }
        else           { bn = g_b[kb * NN + n] + a; }
        float e = __expf(bn);
        es += e;
        #pragma unroll
        for (int o = 0; o < OC; ++o) sa[o] = fmaf(e, uhv[o], sa[o]);
    }

    // warp reduce
    #pragma unroll
    for (int d = 16; d >= 1; d >>= 1) {
        es += __shfl_xor_sync(FULL, es, d);
        #pragma unroll
        for (int o = 0; o < OC; ++o) sa[o] += __shfl_xor_sync(FULL, sa[o], d);
    }
    __shared__ float red[16][OC];
    __shared__ float rede[16];
    if (lane == 0) {
        rede[w] = es;
        #pragma unroll
        for (int o = 0; o < OC; ++o) red[w][o] = sa[o];
    }
    __syncthreads();

    if (w == 0) {
        const int o = lane & 15;
        float s = 0.0f, et = 0.0f;
        #pragma unroll
        for (int i = 0; i < 16; ++i) { s += red[i][o]; et += rede[i]; }
        if (pass == 1) {
            if (lane < 16) g_s[kb * OC + o] = s;
            if (lane == 0) g_es[kb] = et;
        } else {
            float x = s / et;
            float q2 = x * x;
            q2 += __shfl_xor_sync(FULL, q2, 1);
            q2 += __shfl_xor_sync(FULL, q2, 2);
            q2 += __shfl_xor_sync(FULL, q2, 4);
            q2 += __shfl_xor_sync(FULL, q2, 8);
            float vv = x * (q2 / ((1.0f + q2) * sqrtf(q2)));
            if (lane < 16) out[kb * OC + o] = vv;
        }
    }
}

extern "C" void kernel_launch(void* const* d_in, const int* in_sizes, int n_in,
                              void* d_out, int out_size)
{
    const float* u = (const float*)d_in[0];
    const float* W = (const float*)d_in[1];
    if (n_in >= 2 && in_sizes[0] == KC * NN * IC * OC) {
        const float* tp = u; u = W; W = tp;
    }
    float* out = (float*)d_out;

    k_uhat<<<dim3(BB / BCH, KC), 512>>>(u, W);
    k_pass<<<KC * BB, 512>>>(out, 1);
    k_pass<<<KC * BB, 512>>>(out, 2);
}

// round 5
// speedup vs baseline: 1.9156x; 1.2502x over previous
#include <cuda_runtime.h>
#include <cuda_fp16.h>

// DigitCaps dynamic routing — single fully-fused kernel.
// u[B=256, N=1152, IC=8], W[K=10, N=1152, IC=8, OC=16] -> v [K, B, 1, 1, 16]
//
// Block = (k, 4 batches), 576 threads (18 warps), grid (64, 10).
// u_hat fp16 in smem [4][1152][16] (144 KB). Coalesced W loads (o = lane&15),
// u staged via smem chunks. Routing logits in REGISTERS (thread owns rows
// n = t and n = t+576). Iterations: v-compute (64 threads + shfl squash) ->
// phase2a (dot a=<uh,v>, b+=a, e=exp(b) -> smem, es warp-reduced) ->
// phase2b ((o-pair, seg) s-accumulation) -> two-stage partial reduce.
// No global scratch at all.

#define KC   10
#define BB   256
#define NN   1152
#define IC   8
#define OC   16
#define TPB  576
#define NW   18
#define BPB  4
#define NCH  144      // n per staged chunk
#define NCHK 8
#define NSEG 72
#define FULL 0xffffffffu

__global__ __launch_bounds__(TPB, 1)
void digitcaps_fused(const float* __restrict__ u,
                     const float* __restrict__ W,
                     float* __restrict__ out)
{
    extern __shared__ char sm[];
    half*  uh   = (half*)sm;                                   // [4][1152][16] = 147456 B
    float* buf  = (float*)(sm + BPB * NN * OC * 2);            // us[4][144][8] | eb[4][1152] (18432 B)
    float* sp   = buf  + BPB * NN;                             // [4][72][16]   (18432 B)
    float* sp2  = sp   + BPB * NSEG * OC;                      // [4][4][16]    (1024 B)
    float* redS = sp2  + BPB * 4 * OC;                         // [18][4][16]   (4608 B)
    float* rede = redS + NW * BPB * OC;                        // [18][4]       (288 B)
    float* vB   = rede + NW * BPB;                             // [4][16]       (256 B)

    const int k    = blockIdx.y;
    const int b0   = blockIdx.x * BPB;
    const int t    = threadIdx.x;
    const int w    = t >> 5;
    const int lane = t & 31;
    const int o    = t & 15;       // phase1 / reductions
    const int ns   = t >> 4;       // 0..35
    const int op   = t & 7;        // phase2b o-pair
    const int seg  = t >> 3;       // 0..71

    // ---------------- phase 1: u_hat + iteration-0 sums ----------------
    float s0[BPB] = {0.f, 0.f, 0.f, 0.f};
    const float* Wk = W + (size_t)k * NN * (IC * OC);

    for (int c = 0; c < NCHK; ++c) {
        __syncthreads();
        // stage u[b0..b0+3][c*144 .. +143][0..7]  (1152 float4, 2 per thread)
        #pragma unroll
        for (int q = 0; q < 2; ++q) {
            int idx = t + q * TPB;                 // 0..1151
            int bb = idx / 288;
            int r  = idx - bb * 288;
            int nn = r >> 1, h = r & 1;
            const float4* src =
                (const float4*)(u + ((size_t)(b0 + bb) * NN + c * NCH + nn) * IC);
            *((float4*)(buf + (bb * NCH + nn) * IC + h * 4)) = src[h];
        }
        __syncthreads();
        #pragma unroll
        for (int j = 0; j < 4; ++j) {
            const int nl = j * 36 + ns;
            const int n  = c * NCH + nl;
            const float* Wr = Wk + (size_t)n * (IC * OC) + o;
            float w0 = Wr[0],  w1 = Wr[16], w2 = Wr[32],  w3 = Wr[48];
            float w4 = Wr[64], w5 = Wr[80], w6 = Wr[96],  w7 = Wr[112];
            #pragma unroll
            for (int bb = 0; bb < BPB; ++bb) {
                const float* ur = buf + (bb * NCH + nl) * IC;
                float4 a0 = *(const float4*)ur;
                float4 a1 = *(const float4*)(ur + 4);
                float acc = a0.x*w0 + a0.y*w1 + a0.z*w2 + a0.w*w3
                          + a1.x*w4 + a1.y*w5 + a1.z*w6 + a1.w*w7;
                s0[bb] += acc;
                uh[((size_t)bb * NN + n) * OC + o] = __float2half_rn(acc);
            }
        }
    }
    // s0 partials: combine lane pairs (same o), stash per-warp
    #pragma unroll
    for (int bb = 0; bb < BPB; ++bb)
        s0[bb] += __shfl_xor_sync(FULL, s0[bb], 16);
    if (lane < 16) {
        #pragma unroll
        for (int bb = 0; bb < BPB; ++bb)
            redS[(w * BPB + bb) * OC + o] = s0[bb];
    }
    __syncthreads();

    // ---------------- routing iterations ----------------
    float br[BPB][2];   // logits for rows n = t, t+576 (per batch), registers

    #pragma unroll 1
    for (int it = 0; it < 3; ++it) {
        // v-compute: 64 threads, one per (bb, o)
        if (t < 64) {
            const int bb = t >> 4, oo = t & 15;
            float s = 0.0f, S;
            if (it == 0) {
                #pragma unroll
                for (int q = 0; q < NW; ++q) s += redS[(q * BPB + bb) * OC + oo];
                S = (float)NN;
            } else {
                #pragma unroll
                for (int q = 0; q < 4; ++q) s += sp2[(bb * 4 + q) * OC + oo];
                S = 0.0f;
                #pragma unroll
                for (int q = 0; q < NW; ++q) S += rede[q * BPB + bb];
            }
            float x = s / S;
            float sq = x * x;
            sq += __shfl_xor_sync(FULL, sq, 1);
            sq += __shfl_xor_sync(FULL, sq, 2);
            sq += __shfl_xor_sync(FULL, sq, 4);
            sq += __shfl_xor_sync(FULL, sq, 8);
            float vv = x * (sq / ((1.0f + sq) * sqrtf(sq)));
            if (it == 2)
                out[((size_t)k * BB + (b0 + bb)) * OC + oo] = vv;
            else
                vB[bb * OC + oo] = vv;
        }
        if (it == 2) return;
        __syncthreads();

        // phase2a: a = <uh, v>, b += a, e = exp(b) -> eb(buf), es per warp
        float* eb = buf;
        #pragma unroll
        for (int bb = 0; bb < BPB; ++bb) {
            const float4 v0 = *(const float4*)(vB + bb * OC + 0);
            const float4 v1 = *(const float4*)(vB + bb * OC + 4);
            const float4 v2 = *(const float4*)(vB + bb * OC + 8);
            const float4 v3 = *(const float4*)(vB + bb * OC + 12);
            float esb = 0.0f;
            #pragma unroll
            for (int r = 0; r < 2; ++r) {
                const int n = t + r * TPB;
                const uint4* rp = (const uint4*)(uh + ((size_t)bb * NN + n) * OC);
                uint4 q0 = rp[0], q1 = rp[1];
                const half2* h0 = (const half2*)&q0;
                const half2* h1 = (const half2*)&q1;
                float a = 0.0f;
                float2 p;
                p = __half22float2(h0[0]); a = fmaf(p.x, v0.x, a); a = fmaf(p.y, v0.y, a);
                p = __half22float2(h0[1]); a = fmaf(p.x, v0.z, a); a = fmaf(p.y, v0.w, a);
                p = __half22float2(h0[2]); a = fmaf(p.x, v1.x, a); a = fmaf(p.y, v1.y, a);
                p = __half22float2(h0[3]); a = fmaf(p.x, v1.z, a); a = fmaf(p.y, v1.w, a);
                p = __half22float2(h1[0]); a = fmaf(p.x, v2.x, a); a = fmaf(p.y, v2.y, a);
                p = __half22float2(h1[1]); a = fmaf(p.x, v2.z, a); a = fmaf(p.y, v2.w, a);
                p = __half22float2(h1[2]); a = fmaf(p.x, v3.x, a); a = fmaf(p.y, v3.y, a);
                p = __half22float2(h1[3]); a = fmaf(p.x, v3.z, a); a = fmaf(p.y, v3.w, a);
                float bn = (it == 0) ? a : (br[bb][r] + a);
                br[bb][r] = bn;
                float e = __expf(bn);
                esb += e;
                eb[bb * NN + n] = e;
            }
            #pragma unroll
            for (int d = 16; d >= 1; d >>= 1)
                esb += __shfl_xor_sync(FULL, esb, d);
            if (lane == 0) rede[w * BPB + bb] = esb;
        }
        __syncthreads();

        // phase2b: s accumulation, thread (seg, op) over 16 rows, 2 o's
        #pragma unroll
        for (int bb = 0; bb < BPB; ++bb) {
            const float* ebb = eb + bb * NN;
            const half*  ub  = uh + (size_t)bb * NN * OC;
            float sx = 0.0f, sy = 0.0f;
            #pragma unroll
            for (int i = 0; i < 16; ++i) {
                const int n = seg * 16 + i;
                float e = ebb[n];
                float2 p = __half22float2(*(const half2*)(ub + n * OC + op * 2));
                sx = fmaf(e, p.x, sx);
                sy = fmaf(e, p.y, sy);
            }
            *(float2*)(sp + ((size_t)bb * NSEG + seg) * OC + op * 2) =
                make_float2(sx, sy);
        }
        __syncthreads();

        // stage A: 72 partials -> 4 per (bb, o)
        if (t < 256) {
            const int bb = t >> 6, q = (t >> 4) & 3, oo = t & 15;
            float s = 0.0f;
            #pragma unroll
            for (int r = 0; r < 18; ++r)
                s += sp[((size_t)bb * NSEG + q * 18 + r) * OC + oo];
            sp2[(bb * 4 + q) * OC + oo] = s;
        }
        __syncthreads();
    }
}

extern "C" void kernel_launch(void* const* d_in, const int* in_sizes, int n_in,
                              void* d_out, int out_size)
{
    const float* u = (const float*)d_in[0];
    const float* W = (const float*)d_in[1];
    if (n_in >= 2 && in_sizes[0] == KC * NN * IC * OC) {
        const float* tp = u; u = W; W = tp;
    }
    float* out = (float*)d_out;

    const int smem_bytes =
        BPB * NN * OC * 2                       // uh (fp16)
        + BPB * NN * 4                          // buf (us | eb)
        + BPB * NSEG * OC * 4                   // sp
        + BPB * 4 * OC * 4                      // sp2
        + NW * BPB * OC * 4                     // redS
        + NW * BPB * 4                          // rede
        + BPB * OC * 4;                         // vB

    cudaFuncSetAttribute(digitcaps_fused,
                         cudaFuncAttributeMaxDynamicSharedMemorySize, smem_bytes);

    dim3 grid(BB / BPB, KC);
    digitcaps_fused<<<grid, TPB, smem_bytes>>>(u, W, out);
}